// round 17
// baseline (speedup 1.0000x reference)
#include <cuda_runtime.h>

// LFQ quantizer, v12 — sparse formulation, thread-per-(row,dim) shape.
//
// T=0.01 saturates the softmax: sigmoid(400|x|) == 1.0f exactly in fp32 once
// 400|x| >= ~17. With AU_CUT=30, a dim is "active" iff 400|x_d| < 30 (P~6%);
// probs are nonzero only on the 2^a codes spanned by active dims (E[2^a]~2.3).
// Kept probs are bit-identical to the dense product (validated R16).
//
// Shape: 128 blocks x 448 threads = one thread per (row,dim) for the MUFU
// work; one thread per row for index/masks/scatter; fence/ticket tail.

#define NROW    4096
#define NDIM    14
#define NCODES  16384
#define RPB     32                  // rows per block
#define NT      (RPB * NDIM)        // 448
#define GRID    (NROW / RPB)        // 128
#define NWARP   (NT / 32)           // 14
#define AU_CUT  30.0f

// scratch (__device__ globals; zero-init at load; reset by tail each call)
__device__ float g_avg[NCODES];
__device__ float g_pH[GRID];
__device__ float g_pC[GRID];
__device__ unsigned int g_ticket;

__global__ __launch_bounds__(NT) void lfq_kernel(const float* __restrict__ x,
                                                 float* __restrict__ out)
{
    __shared__ float SQ[RPB][NDIM];        // sigmoid(400*x_d) (signed)
    __shared__ unsigned char SPos[RPB][NDIM];
    __shared__ unsigned char SAct[RPB][NDIM];
    __shared__ float sRed[NT];             // block reduce / tail reduce
    __shared__ float sWH[NWARP], sWC[NWARP];
    __shared__ int sh_last;

    const int t = threadIdx.x;
    const int b = blockIdx.x;
    const int r = t / NDIM;                // row within block
    const int d = t - r * NDIM;            // dim
    const int row0 = b * RPB;

    // ---- per-(row,dim) pass: all MUFU work in parallel ----
    const float xv = x[row0 * NDIM + t];   // coalesced (identity layout)
    const int pos = xv > 0.f ? 1 : 0;
    const float au = fabsf(400.f * xv);
    const float e  = __expf(-au);                   // e^{-|u|}
    const float qmaj = __fdividef(1.f, 1.f + e);    // sigmoid(|u|)
    const float qmin = e * qmaj;                    // sigmoid(-|u|)
    const float h = qmin * au + __logf(1.f + e);    // binary entropy (nats)
    const float cm = fabsf(xv) - 1.f;
    const float c = cm * cm;                        // (x - sign(x))^2

    SQ[r][d]   = pos ? qmaj : qmin;                 // sigmoid(400*x_d)
    SPos[r][d] = (unsigned char)pos;
    SAct[r][d] = (au < AU_CUT) ? 1 : 0;
    out[row0 * NDIM + t] = pos ? 1.f : -1.f;        // quantized, coalesced

    // ---- block H/C reduction (sum over all 448 threads) ----
    float hW = h, cW = c;
#pragma unroll
    for (int off = 16; off > 0; off >>= 1) {
        hW += __shfl_down_sync(0xFFFFFFFFu, hW, off);
        cW += __shfl_down_sync(0xFFFFFFFFu, cW, off);
    }
    if ((t & 31) == 0) { sWH[t >> 5] = hW; sWC[t >> 5] = cW; }
    __syncthreads();
    if (t == 0) {
        float H = 0.f, C = 0.f;
#pragma unroll
        for (int w = 0; w < NWARP; w++) { H += sWH[w]; C += sWC[w]; }
        g_pH[b] = H; g_pC[b] = C;
    }

    // ---- per-row pass: index, masks, sparse scatter ----
    if (t < RPB) {
        const int r2 = t;
        int idx_be = 0, amask = 0, j_in = 0;
#pragma unroll
        for (int dd = 0; dd < NDIM; dd++) {
            const int p = SPos[r2][dd];
            const int a = SAct[r2][dd];
            idx_be |= p << (13 - dd);
            amask  |= a << dd;
            j_in   |= (p & (a ^ 1)) << dd;
        }
        out[NROW * NDIM + row0 + r2] = (float)idx_be;

        // enumerate submasks of the active dims (E[2^a] ~ 2.3)
        unsigned sub = (unsigned)amask;
        while (true) {
            float pr = 1.f;
            unsigned rem = (unsigned)amask;
            while (rem) {
                const int dd = __ffs((int)rem) - 1;
                rem &= rem - 1;
                const float q = SQ[r2][dd];
                pr *= ((sub >> dd) & 1u) ? q : (1.f - q);
            }
            atomicAdd(&g_avg[(unsigned)j_in | sub], pr);
            if (sub == 0u) break;
            sub = (sub - 1u) & (unsigned)amask;
        }
    }

    // ---- ticket: release writes; last block finalizes ----
    __threadfence();
    __syncthreads();
    if (t == 0)
        sh_last = (atomicAdd(&g_ticket, 1u) == GRID - 1) ? 1 : 0;
    __syncthreads();
    if (!sh_last) return;
    __threadfence();                  // acquire side

    // ---- tail (single block): codebook entropy + scalars + state reset ----
    float term = 0.f;
    for (int j = t; j < NCODES; j += NT) {
        const float a = g_avg[j] * (1.f / (float)NROW);
        term += a * __logf(a + 1e-5f);             // a==0 -> 0, matches ref
        g_avg[j] = 0.f;                            // reset for next replay
    }
    sRed[t] = term;
    __syncthreads();
    for (int off = 256; off > 0; off >>= 1) {      // 448 -> tree (guarded)
        if (t < off && t + off < NT) sRed[t] += sRed[t + off];
        __syncthreads();
    }
    const float sumT = sRed[0];

    if (t == 0) {
        float sumH = 0.f, sumC = 0.f;
#pragma unroll
        for (int g = 0; g < GRID; g++) { sumH += g_pH[g]; sumC += g_pC[g]; }
        const float per_sample = sumH * (1.f / (float)NROW);
        const float cb_entropy = -sumT;
        float* sc = out + NROW * NDIM + NROW;
        sc[0] = per_sample;
        sc[1] = cb_entropy;
        sc[2] = per_sample - cb_entropy;
        sc[3] = sumC * (1.f / (float)(NROW * NDIM));
        g_ticket = 0u;                             // reset for next replay
    }
}

extern "C" void kernel_launch(void* const* d_in, const int* in_sizes, int n_in,
                              void* d_out, int out_size)
{
    (void)in_sizes; (void)n_in; (void)out_size;
    const float* x = (const float*)d_in[0];   // [2,2048,14] float32
    float* out = (float*)d_out;

    lfq_kernel<<<GRID, NT>>>(x, out);
}